// round 3
// baseline (speedup 1.0000x reference)
#include <cuda_runtime.h>
#include <cuda_bf16.h>
#include <math.h>

// Problem constants
#define NB   2048
#define NS   64
#define NF   16
#define NH   512
#define N4H  2048
#define NE   8
#define NHOR 8
#define NHH  256

// GEMM tiling
#define BM 128
#define BN 128
#define BKK 8

// ---------------------------------------------------------------------------
// Scratch (device globals; no dynamic allocation allowed)
// ---------------------------------------------------------------------------
__device__ float g_h0[NB * NH];
__device__ float g_c0[NB * NH];
__device__ float g_h1[NB * NH];
__device__ float g_c1[NB * NH];
__device__ float g_z[NB * N4H];          // LSTM pre-activation scratch
__device__ float g_gh[NB * NHH];         // gate hidden
__device__ float g_et[NB * N4H];         // track expert hidden (B, E*HH)
__device__ float g_ei[NB * N4H];         // dwind expert hidden
__device__ float g_ew[NB * N4H];         // wind expert hidden
__device__ float g_gates[NB * NE];
__device__ float g_gsum[NB * NE];
__device__ float g_decin[NB * 8];        // zero-padded decoder input (4 real + 4 pad)
__device__ float g_wpad[N4H * 8];        // dec_Wih zero-padded K=4 -> 8
__device__ float g_trk[NHOR * NB * 2];
__device__ float g_dw[NHOR * NB];
__device__ float g_wa[NHOR * NB];

// ---------------------------------------------------------------------------
// Generic 2-segment NT GEMM:  C(M x N) = A0(M x K0) @ W0(N x K0)^T
//                                      + A1(M x K1) @ W1(N x K1)^T + bias[, relu]
// A row-major with given lda, W row-major (ldw = K), C row-major (ldc = N).
// M = 2048 implied by grid.y * BM. K0, K1 must be multiples of 8 (or 0).
// ---------------------------------------------------------------------------
__global__ __launch_bounds__(256)
void gemm_nt(const float* __restrict__ A0, int lda0,
             const float* __restrict__ W0, int K0,
             const float* __restrict__ A1, int lda1,
             const float* __restrict__ W1, int K1,
             const float* __restrict__ bias,
             float* __restrict__ C, int N, int relu)
{
    __shared__ float As[2][BKK][BM + 4];
    __shared__ float Bs[2][BKK][BN + 4];

    const int tid = threadIdx.x;
    const int m0 = blockIdx.y * BM;
    const int n0 = blockIdx.x * BN;

    const int aRow = tid >> 1;          // 0..127
    const int aCol = (tid & 1) * 4;     // 0 or 4
    const int ty = tid >> 4;            // 0..15
    const int tx = tid & 15;            // 0..15

    float acc[8][8];
#pragma unroll
    for (int i = 0; i < 8; i++)
#pragma unroll
        for (int j = 0; j < 8; j++) acc[i][j] = 0.f;

#pragma unroll 1
    for (int seg = 0; seg < 2; seg++) {
        const float* A  = seg ? A1 : A0;
        const float* W  = seg ? W1 : W0;
        const int lda   = seg ? lda1 : lda0;
        const int K     = seg ? K1 : K0;
        if (K == 0) continue;

        const float* Ab = A + (m0 + aRow) * lda + aCol;
        const float* Wb = W + (n0 + aRow) * K + aCol;
        const int nt = K / BKK;

        __syncthreads();   // protect smem from previous segment's readers
        {
            float4 ra = *(const float4*)Ab;
            float4 rw = *(const float4*)Wb;
            As[0][aCol + 0][aRow] = ra.x;
            As[0][aCol + 1][aRow] = ra.y;
            As[0][aCol + 2][aRow] = ra.z;
            As[0][aCol + 3][aRow] = ra.w;
            Bs[0][aCol + 0][aRow] = rw.x;
            Bs[0][aCol + 1][aRow] = rw.y;
            Bs[0][aCol + 2][aRow] = rw.z;
            Bs[0][aCol + 3][aRow] = rw.w;
        }
        __syncthreads();

        int buf = 0;
#pragma unroll 1
        for (int t = 0; t < nt; t++) {
            float4 na, nw;
            const bool more = (t + 1 < nt);
            if (more) {
                na = *(const float4*)(Ab + (t + 1) * BKK);
                nw = *(const float4*)(Wb + (t + 1) * BKK);
            }
#pragma unroll
            for (int k = 0; k < BKK; k++) {
                float ar[8], br[8];
                *(float4*)(ar)     = *(const float4*)&As[buf][k][ty * 8];
                *(float4*)(ar + 4) = *(const float4*)&As[buf][k][ty * 8 + 4];
                *(float4*)(br)     = *(const float4*)&Bs[buf][k][tx * 8];
                *(float4*)(br + 4) = *(const float4*)&Bs[buf][k][tx * 8 + 4];
#pragma unroll
                for (int i = 0; i < 8; i++)
#pragma unroll
                    for (int j = 0; j < 8; j++)
                        acc[i][j] += ar[i] * br[j];
            }
            if (more) {
                const int nb = buf ^ 1;
                As[nb][aCol + 0][aRow] = na.x;
                As[nb][aCol + 1][aRow] = na.y;
                As[nb][aCol + 2][aRow] = na.z;
                As[nb][aCol + 3][aRow] = na.w;
                Bs[nb][aCol + 0][aRow] = nw.x;
                Bs[nb][aCol + 1][aRow] = nw.y;
                Bs[nb][aCol + 2][aRow] = nw.z;
                Bs[nb][aCol + 3][aRow] = nw.w;
                __syncthreads();
                buf = nb;
            }
        }
    }

    // Epilogue: + bias, optional relu, float4 stores
    float bvec[8];
#pragma unroll
    for (int j = 0; j < 8; j++)
        bvec[j] = bias ? bias[n0 + tx * 8 + j] : 0.f;

#pragma unroll
    for (int i = 0; i < 8; i++) {
        const int m = m0 + ty * 8 + i;
        float* Crow = C + m * N + n0 + tx * 8;
        float v[8];
#pragma unroll
        for (int j = 0; j < 8; j++) {
            float w = acc[i][j] + bvec[j];
            v[j] = relu ? fmaxf(w, 0.f) : w;
        }
        *(float4*)(Crow)     = make_float4(v[0], v[1], v[2], v[3]);
        *(float4*)(Crow + 4) = make_float4(v[4], v[5], v[6], v[7]);
    }
}

// ---------------------------------------------------------------------------
// LSTM pointwise cell: z (B x 4H, gates i,f,g,o) -> update h, c
// ---------------------------------------------------------------------------
__global__ void lstm_cell(const float* __restrict__ z,
                          float* __restrict__ h, float* __restrict__ c)
{
    const int idx = blockIdx.x * blockDim.x + threadIdx.x;   // NB*NH threads
    const int b = idx >> 9;
    const int j = idx & (NH - 1);
    const float* zb = z + b * N4H;
    const float zi = zb[j];
    const float zf = zb[NH + j];
    const float zg = zb[2 * NH + j];
    const float zo = zb[3 * NH + j];
    const float ig = 1.f / (1.f + expf(-zi));
    const float fg = 1.f / (1.f + expf(-zf));
    const float gg = tanhf(zg);
    const float og = 1.f / (1.f + expf(-zo));
    const float c2 = fg * c[idx] + ig * gg;
    c[idx] = c2;
    h[idx] = og * tanhf(c2);
}

// ---------------------------------------------------------------------------
// Gate logits + softmax (warp per batch row). gh is relu(ctx@gW1^T+gb1).
// ---------------------------------------------------------------------------
__global__ void gates_kernel(const float* __restrict__ gh,
                             const float* __restrict__ gW2,
                             const float* __restrict__ gb2,
                             float* __restrict__ gates,
                             float* __restrict__ gsum)
{
    const int warp = threadIdx.x >> 5;
    const int lane = threadIdx.x & 31;
    const int b = blockIdx.x * 8 + warp;
    if (b >= NB) return;

    float acc[NE];
#pragma unroll
    for (int e = 0; e < NE; e++) acc[e] = 0.f;

    const float* row = gh + b * NHH;
    for (int k = lane; k < NHH; k += 32) {
        const float x = row[k];
#pragma unroll
        for (int e = 0; e < NE; e++)
            acc[e] += x * gW2[e * NHH + k];
    }
#pragma unroll
    for (int e = 0; e < NE; e++)
#pragma unroll
        for (int off = 16; off > 0; off >>= 1)
            acc[e] += __shfl_down_sync(0xffffffffu, acc[e], off);

    if (lane == 0) {
        float zv[NE];
        float mx = -1e30f;
#pragma unroll
        for (int e = 0; e < NE; e++) { zv[e] = acc[e] + gb2[e]; mx = fmaxf(mx, zv[e]); }
        float s = 0.f;
#pragma unroll
        for (int e = 0; e < NE; e++) { zv[e] = expf(zv[e] - mx); s += zv[e]; }
        const float inv = 1.f / s;
#pragma unroll
        for (int e = 0; e < NE; e++) {
            const float g = zv[e] * inv;
            gates[b * NE + e] = g;
            gsum[b * NE + e] += g;
        }
    }
}

// ---------------------------------------------------------------------------
// Expert output layer + gate mixing + decoder feedback (warp per batch row)
// ---------------------------------------------------------------------------
__global__ void combine_kernel(const float* __restrict__ et,
                               const float* __restrict__ ei,
                               const float* __restrict__ ew,
                               const float* __restrict__ tW2, const float* __restrict__ tb2,
                               const float* __restrict__ iW2, const float* __restrict__ ib2,
                               const float* __restrict__ wW2, const float* __restrict__ wb2,
                               const float* __restrict__ gates,
                               float* __restrict__ trk, float* __restrict__ dw,
                               float* __restrict__ wa, float* __restrict__ decin,
                               int step)
{
    const int warp = threadIdx.x >> 5;
    const int lane = threadIdx.x & 31;
    const int b = blockIdx.x * 8 + warp;
    if (b >= NB) return;

    float t0 = 0.f, t1 = 0.f, di = 0.f, wv = 0.f;
#pragma unroll 1
    for (int e = 0; e < NE; e++) {
        const int base = b * N4H + e * NHH;
        float a0 = 0.f, a1 = 0.f, ai = 0.f, aw = 0.f;
        for (int hh = lane; hh < NHH; hh += 32) {
            const float vt = et[base + hh];
            a0 += vt * tW2[e * 2 * NHH + hh];
            a1 += vt * tW2[e * 2 * NHH + NHH + hh];
            ai += ei[base + hh] * iW2[e * NHH + hh];
            aw += ew[base + hh] * wW2[e * NHH + hh];
        }
#pragma unroll
        for (int off = 16; off > 0; off >>= 1) {
            a0 += __shfl_down_sync(0xffffffffu, a0, off);
            a1 += __shfl_down_sync(0xffffffffu, a1, off);
            ai += __shfl_down_sync(0xffffffffu, ai, off);
            aw += __shfl_down_sync(0xffffffffu, aw, off);
        }
        if (lane == 0) {
            const float g = gates[b * NE + e];
            t0 += g * (a0 + tb2[e * 2 + 0]);
            t1 += g * (a1 + tb2[e * 2 + 1]);
            di += g * (ai + ib2[e]);
            wv += g * (aw + wb2[e]);
        }
    }
    if (lane == 0) {
        trk[(step * NB + b) * 2 + 0] = t0;
        trk[(step * NB + b) * 2 + 1] = t1;
        dw[step * NB + b] = di;
        wa[step * NB + b] = wv;
        decin[b * 8 + 0] = t0;
        decin[b * 8 + 1] = t1;
        decin[b * 8 + 2] = di;
        decin[b * 8 + 3] = wv;
        // cols 4..7 stay zero (init kernel)
    }
}

// ---------------------------------------------------------------------------
// Per-replay init: zero states, decoder input, gate sums; build padded dec_Wih
// ---------------------------------------------------------------------------
__global__ void init_kernel(const float* __restrict__ dec_Wih,
                            float* __restrict__ h0, float* __restrict__ c0,
                            float* __restrict__ h1, float* __restrict__ c1,
                            float* __restrict__ decin, float* __restrict__ gsum,
                            float* __restrict__ wpad)
{
    const int i = blockIdx.x * blockDim.x + threadIdx.x;
    if (i < NB * NH) { h0[i] = 0.f; c0[i] = 0.f; h1[i] = 0.f; c1[i] = 0.f; }
    if (i < NB * 8)  { decin[i] = 0.f; gsum[i] = 0.f; }
    if (i < N4H * 8) {
        const int r = i >> 3, cc = i & 7;
        wpad[i] = (cc < 4) ? dec_Wih[r * 4 + cc] : 0.f;
    }
}

// ---------------------------------------------------------------------------
// Output assembly: [track(B,16) | intensity(B,8) | wind(B,8) | gates_avg(B,8)]
// ---------------------------------------------------------------------------
__global__ void final_kernel(const float* __restrict__ trk,
                             const float* __restrict__ dw,
                             const float* __restrict__ wa,
                             const float* __restrict__ gsum,
                             float* __restrict__ out)
{
    const int idx = blockIdx.x * blockDim.x + threadIdx.x;
    if (idx >= NB * 40) return;
    const int b = idx / 40;
    const int r = idx % 40;
    if (r < 16) {
        const int o = r >> 3, t = r & 7;
        out[b * 16 + r] = trk[(t * NB + b) * 2 + o];
    } else if (r < 24) {
        const int t = r - 16;
        out[NB * 16 + b * 8 + t] = dw[t * NB + b];
    } else if (r < 32) {
        const int t = r - 24;
        out[NB * 24 + b * 8 + t] = wa[t * NB + b];
    } else {
        const int e = r - 32;
        out[NB * 32 + b * 8 + e] = gsum[b * 8 + e] * (1.f / NHOR);
    }
}

// ---------------------------------------------------------------------------
// Launch
// ---------------------------------------------------------------------------
extern "C" void kernel_launch(void* const* d_in, const int* in_sizes, int n_in,
                              void* d_out, int out_size)
{
    (void)in_sizes; (void)n_in; (void)out_size;

    const float* x        = (const float*)d_in[0];
    const float* eWih0    = (const float*)d_in[1];
    const float* eWhh0    = (const float*)d_in[2];
    const float* eb0      = (const float*)d_in[3];
    const float* eWih1    = (const float*)d_in[4];
    const float* eWhh1    = (const float*)d_in[5];
    const float* eb1      = (const float*)d_in[6];
    const float* dWih     = (const float*)d_in[7];
    const float* dWhh     = (const float*)d_in[8];
    const float* db       = (const float*)d_in[9];
    const float* gW1      = (const float*)d_in[10];
    const float* gb1      = (const float*)d_in[11];
    const float* gW2      = (const float*)d_in[12];
    const float* gb2      = (const float*)d_in[13];
    const float* tW1      = (const float*)d_in[14];
    const float* tb1      = (const float*)d_in[15];
    const float* tW2      = (const float*)d_in[16];
    const float* tb2      = (const float*)d_in[17];
    const float* iW1      = (const float*)d_in[18];
    const float* ib1      = (const float*)d_in[19];
    const float* iW2      = (const float*)d_in[20];
    const float* ib2      = (const float*)d_in[21];
    const float* wW1      = (const float*)d_in[22];
    const float* wb1      = (const float*)d_in[23];
    const float* wW2      = (const float*)d_in[24];
    const float* wb2      = (const float*)d_in[25];
    float* out            = (float*)d_out;

    float *h0, *c0, *h1, *c1, *z, *gh, *et, *ei, *ew;
    float *gates, *gsum, *decin, *wpad, *trk, *dw, *wa;
    cudaGetSymbolAddress((void**)&h0,    g_h0);
    cudaGetSymbolAddress((void**)&c0,    g_c0);
    cudaGetSymbolAddress((void**)&h1,    g_h1);
    cudaGetSymbolAddress((void**)&c1,    g_c1);
    cudaGetSymbolAddress((void**)&z,     g_z);
    cudaGetSymbolAddress((void**)&gh,    g_gh);
    cudaGetSymbolAddress((void**)&et,    g_et);
    cudaGetSymbolAddress((void**)&ei,    g_ei);
    cudaGetSymbolAddress((void**)&ew,    g_ew);
    cudaGetSymbolAddress((void**)&gates, g_gates);
    cudaGetSymbolAddress((void**)&gsum,  g_gsum);
    cudaGetSymbolAddress((void**)&decin, g_decin);
    cudaGetSymbolAddress((void**)&wpad,  g_wpad);
    cudaGetSymbolAddress((void**)&trk,   g_trk);
    cudaGetSymbolAddress((void**)&dw,    g_dw);
    cudaGetSymbolAddress((void**)&wa,    g_wa);

    init_kernel<<<(NB * NH + 255) / 256, 256>>>(dWih, h0, c0, h1, c1, decin, gsum, wpad);

    const dim3 gfull(N4H / BN, NB / BM);   // (16,16)
    const dim3 gsmall(NHH / BN, NB / BM);  // (2,16)
    const int cellBlocks = (NB * NH) / 256;

    // ---- Encoder: 64 steps, two stacked LSTM layers ----
    for (int t = 0; t < NS; t++) {
        // layer 0: z = x_t @ Wih0^T + h0 @ Whh0^T + b0
        gemm_nt<<<gfull, 256>>>(x + t * NF, NS * NF, eWih0, NF,
                                h0, NH, eWhh0, NH, eb0, z, N4H, 0);
        lstm_cell<<<cellBlocks, 256>>>(z, h0, c0);
        // layer 1: z = h0 @ Wih1^T + h1 @ Whh1^T + b1
        gemm_nt<<<gfull, 256>>>(h0, NH, eWih1, NH,
                                h1, NH, eWhh1, NH, eb1, z, N4H, 0);
        lstm_cell<<<cellBlocks, 256>>>(z, h1, c1);
    }

    // ---- Decoder: 8 steps (state continues in h1/c1) ----
    for (int s = 0; s < NHOR; s++) {
        gemm_nt<<<gfull, 256>>>(decin, 8, wpad, 8,
                                h1, NH, dWhh, NH, db, z, N4H, 0);
        lstm_cell<<<cellBlocks, 256>>>(z, h1, c1);

        // gate hidden: relu(ctx @ gW1^T + gb1)
        gemm_nt<<<gsmall, 256>>>(h1, NH, gW1, NH,
                                 (const float*)nullptr, 0, (const float*)nullptr, 0,
                                 gb1, gh, NHH, 1);
        // expert hiddens: relu(ctx @ W1^T + b1), W1 flattened (E*HH, H)
        gemm_nt<<<gfull, 256>>>(h1, NH, tW1, NH,
                                (const float*)nullptr, 0, (const float*)nullptr, 0,
                                tb1, et, N4H, 1);
        gemm_nt<<<gfull, 256>>>(h1, NH, iW1, NH,
                                (const float*)nullptr, 0, (const float*)nullptr, 0,
                                ib1, ei, N4H, 1);
        gemm_nt<<<gfull, 256>>>(h1, NH, wW1, NH,
                                (const float*)nullptr, 0, (const float*)nullptr, 0,
                                wb1, ew, N4H, 1);

        gates_kernel<<<NB / 8, 256>>>(gh, gW2, gb2, gates, gsum);
        combine_kernel<<<NB / 8, 256>>>(et, ei, ew, tW2, tb2, iW2, ib2, wW2, wb2,
                                        gates, trk, dw, wa, decin, s);
    }

    final_kernel<<<(NB * 40 + 255) / 256, 256>>>(trk, dw, wa, gsum, out);
}

// round 7
// speedup vs baseline: 2.4433x; 2.4433x over previous
#include <cuda_runtime.h>
#include <cuda_fp16.h>
#include <math.h>
#include <stdint.h>

// ---------------------------------------------------------------------------
// Problem constants
// ---------------------------------------------------------------------------
#define NB   2048
#define NS   64
#define NF   16
#define NH   512
#define N4H  2048
#define NE   8
#define NHOR 8
#define NHH  256
#define KP   32                 // K padding for tiny-K segments

// GEMM tiling (mma.sync fp16 3-split)
#define BM 256
#define BN 128
#define BK 32
#define PITCH 80                // 64B data + 16B pad -> conflict-free ldmatrix
#define SOFF_AH 0
#define SOFF_AL 20480           // 256*80
#define SOFF_WH 40960
#define SOFF_WL 51200           // +128*80
#define STAGE   61440
#define NSTAGE  3
#define DSMEM   (NSTAGE * STAGE)   // 180 KB

// ---------------------------------------------------------------------------
// Device scratch (no dynamic allocation allowed)
// ---------------------------------------------------------------------------
__device__ __align__(16) float g_c0[NB * NH];
__device__ __align__(16) float g_c1[NB * NH];
__device__ __align__(16) __half g_h0h[NB * NH], g_h0l[NB * NH];
__device__ __align__(16) __half g_h1h[NB * NH], g_h1l[NB * NH];
__device__ __align__(16) float g_z[NB * N4H];
__device__ __align__(16) float g_gh[NB * NHH];
__device__ __align__(16) float g_et[NB * N4H], g_ei[NB * N4H], g_ew[NB * N4H];
__device__ __align__(16) float g_gates[NB * NE], g_gsum[NB * NE];
__device__ __align__(16) __half g_dinh[NB * KP], g_dinl[NB * KP];
__device__ __align__(16) float g_trk[NHOR * NB * 2], g_dw[NHOR * NB], g_wa[NHOR * NB];

// fp16 hi/lo operand buffers
__device__ __align__(16) __half g_xph[NS * NB * KP], g_xpl[NS * NB * KP];
__device__ __align__(16) __half g_wih0h[N4H * KP],  g_wih0l[N4H * KP];
__device__ __align__(16) __half g_whh0h[N4H * NH],  g_whh0l[N4H * NH];
__device__ __align__(16) __half g_wih1h[N4H * NH],  g_wih1l[N4H * NH];
__device__ __align__(16) __half g_whh1h[N4H * NH],  g_whh1l[N4H * NH];
__device__ __align__(16) __half g_dwihh[N4H * KP],  g_dwihl[N4H * KP];
__device__ __align__(16) __half g_dwhhh[N4H * NH],  g_dwhhl[N4H * NH];
__device__ __align__(16) __half g_gw1h[NHH * NH],   g_gw1l[NHH * NH];
__device__ __align__(16) __half g_tw1h[N4H * NH],   g_tw1l[N4H * NH];
__device__ __align__(16) __half g_iw1h[N4H * NH],   g_iw1l[N4H * NH];
__device__ __align__(16) __half g_ww1h[N4H * NH],   g_ww1l[N4H * NH];

// ---------------------------------------------------------------------------
// PTX helpers (baseline features only: cp.async, ldmatrix, mma.sync)
// ---------------------------------------------------------------------------
__device__ __forceinline__ uint32_t smem_u32(const void* p) {
    return (uint32_t)__cvta_generic_to_shared(p);
}
__device__ __forceinline__ void cp16(uint32_t s, const void* g) {
    asm volatile("cp.async.cg.shared.global [%0], [%1], 16;" :: "r"(s), "l"(g));
}
__device__ __forceinline__ void cp_commit() {
    asm volatile("cp.async.commit_group;" ::: "memory");
}
__device__ __forceinline__ void cp_wait0() { asm volatile("cp.async.wait_group 0;" ::: "memory"); }
__device__ __forceinline__ void cp_wait1() { asm volatile("cp.async.wait_group 1;" ::: "memory"); }
__device__ __forceinline__ void cp_wait2() { asm volatile("cp.async.wait_group 2;" ::: "memory"); }

__device__ __forceinline__ void ldsm4(uint32_t* r, uint32_t addr) {
    asm volatile("ldmatrix.sync.aligned.m8n8.x4.shared.b16 {%0,%1,%2,%3}, [%4];"
                 : "=r"(r[0]), "=r"(r[1]), "=r"(r[2]), "=r"(r[3]) : "r"(addr));
}
__device__ __forceinline__ void mma_f16(float* c, const uint32_t* a, const uint32_t* b) {
    asm volatile(
        "mma.sync.aligned.m16n8k16.row.col.f32.f16.f16.f32 "
        "{%0,%1,%2,%3}, {%4,%5,%6,%7}, {%8,%9}, {%0,%1,%2,%3};"
        : "+f"(c[0]), "+f"(c[1]), "+f"(c[2]), "+f"(c[3])
        : "r"(a[0]), "r"(a[1]), "r"(a[2]), "r"(a[3]), "r"(b[0]), "r"(b[1]));
}

// ---------------------------------------------------------------------------
// fp16 3-split NT GEMM:
//   C(2048 x N) = sum_seg [Aseg @ Wseg^T] + bias [, relu]
// A (rows x K) fp16 hi/lo row-major, W (N x K) fp16 hi/lo row-major (K-major).
// 3-term emulation: AhWh + AhWl + AlWh, fp32 accumulate. K per segment = nt*32.
// ---------------------------------------------------------------------------
__global__ void __launch_bounds__(256, 1)
gemm_f16x3(const __half* __restrict__ A0h, const __half* __restrict__ A0l, int lda0,
           const __half* __restrict__ W0h, const __half* __restrict__ W0l, int ldw0, int nt0,
           const __half* __restrict__ A1h, const __half* __restrict__ A1l, int lda1,
           const __half* __restrict__ W1h, const __half* __restrict__ W1l, int ldw1, int nt1,
           const float* __restrict__ bias, float* __restrict__ C, int ldc, int relu)
{
    extern __shared__ char dsm[];
    const uint32_t sbase = smem_u32(dsm);

    const int tid  = threadIdx.x;
    const int wid  = tid >> 5;
    const int lane = tid & 31;
    const int m0   = blockIdx.y * BM;
    const int n0   = blockIdx.x * BN;
    const int nt   = nt0 + nt1;

    const int wm = (wid & 3) * 64;
    const int wn = (wid >> 2) * 64;

    // lane-invariant smem fragment offsets (bytes)
    const uint32_t a_off = (uint32_t)(wm + (lane & 15)) * PITCH + ((lane >> 4) << 4);
    const uint32_t b_off = (uint32_t)(wn + (lane & 7) + ((lane >> 4) << 3)) * PITCH
                         + (((lane >> 3) & 1) << 4);

    float c[4][8][4];
#pragma unroll
    for (int i = 0; i < 4; i++)
#pragma unroll
        for (int j = 0; j < 8; j++)
#pragma unroll
            for (int k = 0; k < 4; k++) c[i][j][k] = 0.f;

    auto load_tile = [&](int t, int buf) {
        const __half *Ah, *Al, *Wh, *Wl;
        int lda, ldw, kb;
        if (t < nt0) { Ah = A0h; Al = A0l; Wh = W0h; Wl = W0l; lda = lda0; ldw = ldw0; kb = t * BK; }
        else         { Ah = A1h; Al = A1l; Wh = W1h; Wl = W1l; lda = lda1; ldw = ldw1; kb = (t - nt0) * BK; }
        const uint32_t sb = sbase + (uint32_t)buf * STAGE;
#pragma unroll
        for (int i = tid; i < BM * 4; i += 256) {
            const int r = i >> 2, cc = i & 3;
            const uint32_t d = sb + SOFF_AH + (uint32_t)r * PITCH + cc * 16;
            const size_t go = ((size_t)(m0 + r) * lda + kb + cc * 8) * 2;
            cp16(d, (const char*)Ah + go);
            cp16(d + (SOFF_AL - SOFF_AH), (const char*)Al + go);
        }
#pragma unroll
        for (int i = tid; i < BN * 4; i += 256) {
            const int r = i >> 2, cc = i & 3;
            const uint32_t d = sb + SOFF_WH + (uint32_t)r * PITCH + cc * 16;
            const size_t go = ((size_t)(n0 + r) * ldw + kb + cc * 8) * 2;
            cp16(d, (const char*)Wh + go);
            cp16(d + (SOFF_WL - SOFF_WH), (const char*)Wl + go);
        }
        cp_commit();
    };

    auto compute_tile = [&](int buf) {
        const uint32_t sb = sbase + (uint32_t)buf * STAGE;
#pragma unroll
        for (int ks = 0; ks < 2; ks++) {
            uint32_t bhi[16], blo[16], a[16];
#pragma unroll
            for (int j = 0; j < 4; j++) {
                const uint32_t baddr = sb + SOFF_WH + b_off + j * (16 * PITCH) + ks * 32;
                ldsm4(&bhi[4 * j], baddr);
                ldsm4(&blo[4 * j], baddr + (SOFF_WL - SOFF_WH));
            }
#pragma unroll
            for (int mt = 0; mt < 4; mt++)
                ldsm4(&a[4 * mt], sb + SOFF_AH + a_off + mt * (16 * PITCH) + ks * 32);
#pragma unroll
            for (int mt = 0; mt < 4; mt++)
#pragma unroll
                for (int j = 0; j < 8; j++) {
                    mma_f16(c[mt][j], &a[4 * mt], &bhi[2 * j]);
                    mma_f16(c[mt][j], &a[4 * mt], &blo[2 * j]);
                }
#pragma unroll
            for (int mt = 0; mt < 4; mt++)
                ldsm4(&a[4 * mt], sb + SOFF_AL + a_off + mt * (16 * PITCH) + ks * 32);
#pragma unroll
            for (int mt = 0; mt < 4; mt++)
#pragma unroll
                for (int j = 0; j < 8; j++)
                    mma_f16(c[mt][j], &a[4 * mt], &bhi[2 * j]);
        }
    };

    // 3-stage pipeline
    load_tile(0, 0);
    if (nt > 1) load_tile(1, 1);
    if (nt > 2) load_tile(2, 2);

#pragma unroll 1
    for (int t = 0; t < nt; t++) {
        if (t + 2 < nt) cp_wait2();
        else if (t + 1 < nt) cp_wait1();
        else cp_wait0();
        __syncthreads();
        compute_tile(t % 3);
        __syncthreads();
        if (t + 3 < nt) load_tile(t + 3, t % 3);
    }

    // Epilogue: +bias, optional relu, float2 stores
#pragma unroll
    for (int mt = 0; mt < 4; mt++) {
        const int row0 = m0 + wm + mt * 16 + (lane >> 2);
#pragma unroll
        for (int j = 0; j < 8; j++) {
            const int col = n0 + wn + j * 8 + (lane & 3) * 2;
            const float b0 = bias[col];
            const float b1 = bias[col + 1];
            float v0 = c[mt][j][0] + b0, v1 = c[mt][j][1] + b1;
            float v2 = c[mt][j][2] + b0, v3 = c[mt][j][3] + b1;
            if (relu) {
                v0 = fmaxf(v0, 0.f); v1 = fmaxf(v1, 0.f);
                v2 = fmaxf(v2, 0.f); v3 = fmaxf(v3, 0.f);
            }
            *(float2*)(C + (size_t)row0 * ldc + col)       = make_float2(v0, v1);
            *(float2*)(C + (size_t)(row0 + 8) * ldc + col) = make_float2(v2, v3);
        }
    }
}

// ---------------------------------------------------------------------------
// LSTM pointwise cell: z (B x 4H) -> update c; emit h as fp16 hi/lo
// ---------------------------------------------------------------------------
__global__ void lstm_cell(const float* __restrict__ z, float* __restrict__ c,
                          __half* __restrict__ hh, __half* __restrict__ hl)
{
    const int idx = blockIdx.x * blockDim.x + threadIdx.x;
    const int b = idx >> 9;
    const int j = idx & (NH - 1);
    const float* zb = z + b * N4H;
    const float zi = zb[j];
    const float zf = zb[NH + j];
    const float zg = zb[2 * NH + j];
    const float zo = zb[3 * NH + j];
    const float ig = 1.f / (1.f + expf(-zi));
    const float fg = 1.f / (1.f + expf(-zf));
    const float gg = tanhf(zg);
    const float og = 1.f / (1.f + expf(-zo));
    const float c2 = fg * c[idx] + ig * gg;
    c[idx] = c2;
    const float h = og * tanhf(c2);
    const __half hi = __float2half_rn(h);
    hh[idx] = hi;
    hl[idx] = __float2half_rn(h - __half2float(hi));
}

// ---------------------------------------------------------------------------
// Gate logits + softmax (warp per batch row)
// ---------------------------------------------------------------------------
__global__ void gates_kernel(const float* __restrict__ gh,
                             const float* __restrict__ gW2,
                             const float* __restrict__ gb2,
                             float* __restrict__ gates,
                             float* __restrict__ gsum)
{
    const int warp = threadIdx.x >> 5;
    const int lane = threadIdx.x & 31;
    const int b = blockIdx.x * 8 + warp;
    if (b >= NB) return;

    float acc[NE];
#pragma unroll
    for (int e = 0; e < NE; e++) acc[e] = 0.f;

    const float* row = gh + b * NHH;
    for (int k = lane; k < NHH; k += 32) {
        const float x = row[k];
#pragma unroll
        for (int e = 0; e < NE; e++) acc[e] += x * gW2[e * NHH + k];
    }
#pragma unroll
    for (int e = 0; e < NE; e++)
#pragma unroll
        for (int off = 16; off > 0; off >>= 1)
            acc[e] += __shfl_down_sync(0xffffffffu, acc[e], off);

    if (lane == 0) {
        float zv[NE];
        float mx = -1e30f;
#pragma unroll
        for (int e = 0; e < NE; e++) { zv[e] = acc[e] + gb2[e]; mx = fmaxf(mx, zv[e]); }
        float s = 0.f;
#pragma unroll
        for (int e = 0; e < NE; e++) { zv[e] = expf(zv[e] - mx); s += zv[e]; }
        const float inv = 1.f / s;
#pragma unroll
        for (int e = 0; e < NE; e++) {
            const float g = zv[e] * inv;
            gates[b * NE + e] = g;
            gsum[b * NE + e] += g;
        }
    }
}

// ---------------------------------------------------------------------------
// Expert output layer + gate mixing + decoder feedback (warp per batch row)
// ---------------------------------------------------------------------------
__global__ void combine_kernel(const float* __restrict__ et,
                               const float* __restrict__ ei,
                               const float* __restrict__ ew,
                               const float* __restrict__ tW2, const float* __restrict__ tb2,
                               const float* __restrict__ iW2, const float* __restrict__ ib2,
                               const float* __restrict__ wW2, const float* __restrict__ wb2,
                               const float* __restrict__ gates,
                               float* __restrict__ trk, float* __restrict__ dw,
                               float* __restrict__ wa,
                               __half* __restrict__ dinh, __half* __restrict__ dinl,
                               int step)
{
    const int warp = threadIdx.x >> 5;
    const int lane = threadIdx.x & 31;
    const int b = blockIdx.x * 8 + warp;
    if (b >= NB) return;

    float t0 = 0.f, t1 = 0.f, di = 0.f, wv = 0.f;
#pragma unroll 1
    for (int e = 0; e < NE; e++) {
        const int base = b * N4H + e * NHH;
        float a0 = 0.f, a1 = 0.f, ai = 0.f, aw = 0.f;
        for (int hh = lane; hh < NHH; hh += 32) {
            const float vt = et[base + hh];
            a0 += vt * tW2[e * 2 * NHH + hh];
            a1 += vt * tW2[e * 2 * NHH + NHH + hh];
            ai += ei[base + hh] * iW2[e * NHH + hh];
            aw += ew[base + hh] * wW2[e * NHH + hh];
        }
#pragma unroll
        for (int off = 16; off > 0; off >>= 1) {
            a0 += __shfl_down_sync(0xffffffffu, a0, off);
            a1 += __shfl_down_sync(0xffffffffu, a1, off);
            ai += __shfl_down_sync(0xffffffffu, ai, off);
            aw += __shfl_down_sync(0xffffffffu, aw, off);
        }
        if (lane == 0) {
            const float g = gates[b * NE + e];
            t0 += g * (a0 + tb2[e * 2 + 0]);
            t1 += g * (a1 + tb2[e * 2 + 1]);
            di += g * (ai + ib2[e]);
            wv += g * (aw + wb2[e]);
        }
    }
    if (lane == 0) {
        trk[(step * NB + b) * 2 + 0] = t0;
        trk[(step * NB + b) * 2 + 1] = t1;
        dw[step * NB + b] = di;
        wa[step * NB + b] = wv;
        float vals[4] = {t0, t1, di, wv};
#pragma unroll
        for (int k = 0; k < 4; k++) {
            const __half hi = __float2half_rn(vals[k]);
            dinh[b * KP + k] = hi;
            dinl[b * KP + k] = __float2half_rn(vals[k] - __half2float(hi));
        }
    }
}

// ---------------------------------------------------------------------------
// Per-replay init: zero states, decoder input (padded), gate sums
// ---------------------------------------------------------------------------
__global__ void init_kernel(float* __restrict__ c0, float* __restrict__ c1,
                            __half* __restrict__ h0h, __half* __restrict__ h0l,
                            __half* __restrict__ h1h, __half* __restrict__ h1l,
                            __half* __restrict__ dinh, __half* __restrict__ dinl,
                            float* __restrict__ gsum)
{
    const int i = blockIdx.x * blockDim.x + threadIdx.x;
    const __half zh = __float2half_rn(0.f);
    if (i < NB * NH) {
        c0[i] = 0.f; c1[i] = 0.f;
        h0h[i] = zh; h0l[i] = zh; h1h[i] = zh; h1l[i] = zh;
    }
    if (i < NB * KP) { dinh[i] = zh; dinl[i] = zh; }
    if (i < NB * NE) gsum[i] = 0.f;
}

// ---------------------------------------------------------------------------
// Weight conversion fp32 -> fp16 hi/lo with K padding
// ---------------------------------------------------------------------------
__global__ void cvt_pad(const float* __restrict__ src,
                        __half* __restrict__ dh, __half* __restrict__ dl,
                        int rows, int kin, int kout)
{
    const int i = blockIdx.x * blockDim.x + threadIdx.x;
    if (i >= rows * kout) return;
    const int r = i / kout, cc = i % kout;
    const float v = (cc < kin) ? src[r * kin + cc] : 0.f;
    const __half hi = __float2half_rn(v);
    dh[i] = hi;
    dl[i] = __float2half_rn(v - __half2float(hi));
}

// x (B,S,F) -> xpad (S, B, KP) fp16 hi/lo, cols >= F zero
__global__ void cvt_x(const float* __restrict__ x,
                      __half* __restrict__ xh, __half* __restrict__ xl)
{
    const int i = blockIdx.x * blockDim.x + threadIdx.x;
    if (i >= NS * NB * KP) return;
    const int t = i / (NB * KP);
    const int b = (i / KP) % NB;
    const int cc = i % KP;
    const float v = (cc < NF) ? x[(size_t)b * NS * NF + t * NF + cc] : 0.f;
    const __half hi = __float2half_rn(v);
    xh[i] = hi;
    xl[i] = __float2half_rn(v - __half2float(hi));
}

// ---------------------------------------------------------------------------
// Output assembly
// ---------------------------------------------------------------------------
__global__ void final_kernel(const float* __restrict__ trk,
                             const float* __restrict__ dw,
                             const float* __restrict__ wa,
                             const float* __restrict__ gsum,
                             float* __restrict__ out)
{
    const int idx = blockIdx.x * blockDim.x + threadIdx.x;
    if (idx >= NB * 40) return;
    const int b = idx / 40;
    const int r = idx % 40;
    if (r < 16) {
        const int o = r >> 3, t = r & 7;
        out[b * 16 + r] = trk[(t * NB + b) * 2 + o];
    } else if (r < 24) {
        const int t = r - 16;
        out[NB * 16 + b * 8 + t] = dw[t * NB + b];
    } else if (r < 32) {
        const int t = r - 24;
        out[NB * 24 + b * 8 + t] = wa[t * NB + b];
    } else {
        const int e = r - 32;
        out[NB * 32 + b * 8 + e] = gsum[b * 8 + e] * (1.f / NHOR);
    }
}

// ---------------------------------------------------------------------------
// Launch
// ---------------------------------------------------------------------------
extern "C" void kernel_launch(void* const* d_in, const int* in_sizes, int n_in,
                              void* d_out, int out_size)
{
    (void)in_sizes; (void)n_in; (void)out_size;

    const float* x     = (const float*)d_in[0];
    const float* eWih0 = (const float*)d_in[1];
    const float* eWhh0 = (const float*)d_in[2];
    const float* eb0   = (const float*)d_in[3];
    const float* eWih1 = (const float*)d_in[4];
    const float* eWhh1 = (const float*)d_in[5];
    const float* eb1   = (const float*)d_in[6];
    const float* dWih  = (const float*)d_in[7];
    const float* dWhh  = (const float*)d_in[8];
    const float* db    = (const float*)d_in[9];
    const float* gW1   = (const float*)d_in[10];
    const float* gb1   = (const float*)d_in[11];
    const float* gW2   = (const float*)d_in[12];
    const float* gb2   = (const float*)d_in[13];
    const float* tW1   = (const float*)d_in[14];
    const float* tb1   = (const float*)d_in[15];
    const float* tW2   = (const float*)d_in[16];
    const float* tb2   = (const float*)d_in[17];
    const float* iW1   = (const float*)d_in[18];
    const float* ib1   = (const float*)d_in[19];
    const float* iW2   = (const float*)d_in[20];
    const float* ib2   = (const float*)d_in[21];
    const float* wW1   = (const float*)d_in[22];
    const float* wb1   = (const float*)d_in[23];
    const float* wW2   = (const float*)d_in[24];
    const float* wb2   = (const float*)d_in[25];
    float* out         = (float*)d_out;

    cudaFuncSetAttribute(gemm_f16x3, cudaFuncAttributeMaxDynamicSharedMemorySize, DSMEM);

    float *c0, *c1, *z, *gh, *et, *ei, *ew, *gates, *gsum, *trk, *dw, *wa;
    __half *h0h, *h0l, *h1h, *h1l, *dinh, *dinl, *xph, *xpl;
    __half *wih0h, *wih0l, *whh0h, *whh0l, *wih1h, *wih1l, *whh1h, *whh1l;
    __half *dwihh, *dwihl, *dwhhh, *dwhhl, *gw1h, *gw1l;
    __half *tw1h, *tw1l, *iw1h, *iw1l, *ww1h, *ww1l;

    cudaGetSymbolAddress((void**)&c0, g_c0);
    cudaGetSymbolAddress((void**)&c1, g_c1);
    cudaGetSymbolAddress((void**)&z, g_z);
    cudaGetSymbolAddress((void**)&gh, g_gh);
    cudaGetSymbolAddress((void**)&et, g_et);
    cudaGetSymbolAddress((void**)&ei, g_ei);
    cudaGetSymbolAddress((void**)&ew, g_ew);
    cudaGetSymbolAddress((void**)&gates, g_gates);
    cudaGetSymbolAddress((void**)&gsum, g_gsum);
    cudaGetSymbolAddress((void**)&trk, g_trk);
    cudaGetSymbolAddress((void**)&dw, g_dw);
    cudaGetSymbolAddress((void**)&wa, g_wa);
    cudaGetSymbolAddress((void**)&h0h, g_h0h);
    cudaGetSymbolAddress((void**)&h0l, g_h0l);
    cudaGetSymbolAddress((void**)&h1h, g_h1h);
    cudaGetSymbolAddress((void**)&h1l, g_h1l);
    cudaGetSymbolAddress((void**)&dinh, g_dinh);
    cudaGetSymbolAddress((void**)&dinl, g_dinl);
    cudaGetSymbolAddress((void**)&xph, g_xph);
    cudaGetSymbolAddress((void**)&xpl, g_xpl);
    cudaGetSymbolAddress((void**)&wih0h, g_wih0h);
    cudaGetSymbolAddress((void**)&wih0l, g_wih0l);
    cudaGetSymbolAddress((void**)&whh0h, g_whh0h);
    cudaGetSymbolAddress((void**)&whh0l, g_whh0l);
    cudaGetSymbolAddress((void**)&wih1h, g_wih1h);
    cudaGetSymbolAddress((void**)&wih1l, g_wih1l);
    cudaGetSymbolAddress((void**)&whh1h, g_whh1h);
    cudaGetSymbolAddress((void**)&whh1l, g_whh1l);
    cudaGetSymbolAddress((void**)&dwihh, g_dwihh);
    cudaGetSymbolAddress((void**)&dwihl, g_dwihl);
    cudaGetSymbolAddress((void**)&dwhhh, g_dwhhh);
    cudaGetSymbolAddress((void**)&dwhhl, g_dwhhl);
    cudaGetSymbolAddress((void**)&gw1h, g_gw1h);
    cudaGetSymbolAddress((void**)&gw1l, g_gw1l);
    cudaGetSymbolAddress((void**)&tw1h, g_tw1h);
    cudaGetSymbolAddress((void**)&tw1l, g_tw1l);
    cudaGetSymbolAddress((void**)&iw1h, g_iw1h);
    cudaGetSymbolAddress((void**)&iw1l, g_iw1l);
    cudaGetSymbolAddress((void**)&ww1h, g_ww1h);
    cudaGetSymbolAddress((void**)&ww1l, g_ww1l);

    // init + conversions (each replay; deterministic)
    init_kernel<<<(NB * NH + 255) / 256, 256>>>(c0, c1, h0h, h0l, h1h, h1l, dinh, dinl, gsum);
    cvt_pad<<<(N4H * KP + 255) / 256, 256>>>(eWih0, wih0h, wih0l, N4H, NF, KP);
    cvt_pad<<<(N4H * NH + 255) / 256, 256>>>(eWhh0, whh0h, whh0l, N4H, NH, NH);
    cvt_pad<<<(N4H * NH + 255) / 256, 256>>>(eWih1, wih1h, wih1l, N4H, NH, NH);
    cvt_pad<<<(N4H * NH + 255) / 256, 256>>>(eWhh1, whh1h, whh1l, N4H, NH, NH);
    cvt_pad<<<(N4H * KP + 255) / 256, 256>>>(dWih, dwihh, dwihl, N4H, 4, KP);
    cvt_pad<<<(N4H * NH + 255) / 256, 256>>>(dWhh, dwhhh, dwhhl, N4H, NH, NH);
    cvt_pad<<<(NHH * NH + 255) / 256, 256>>>(gW1, gw1h, gw1l, NHH, NH, NH);
    cvt_pad<<<(N4H * NH + 255) / 256, 256>>>(tW1, tw1h, tw1l, N4H, NH, NH);
    cvt_pad<<<(N4H * NH + 255) / 256, 256>>>(iW1, iw1h, iw1l, N4H, NH, NH);
    cvt_pad<<<(N4H * NH + 255) / 256, 256>>>(wW1, ww1h, ww1l, N4H, NH, NH);
    cvt_x<<<(NS * NB * KP + 255) / 256, 256>>>(x, xph, xpl);

    const dim3 gfull(N4H / BN, NB / BM);   // (16, 8)
    const dim3 ggate(NHH / BN, NB / BM);   // (2, 8)
    const int cellBlocks = (NB * NH) / 256;
    const int NTH = NH / BK;               // 16

    // ---- Encoder: 64 steps, two stacked LSTM layers ----
    for (int t = 0; t < NS; t++) {
        gemm_f16x3<<<gfull, 256, DSMEM>>>(
            xph + (size_t)t * NB * KP, xpl + (size_t)t * NB * KP, KP,
            wih0h, wih0l, KP, 1,
            h0h, h0l, NH, whh0h, whh0l, NH, NTH,
            eb0, z, N4H, 0);
        lstm_cell<<<cellBlocks, 256>>>(z, c0, h0h, h0l);

        gemm_f16x3<<<gfull, 256, DSMEM>>>(
            h0h, h0l, NH, wih1h, wih1l, NH, NTH,
            h1h, h1l, NH, whh1h, whh1l, NH, NTH,
            eb1, z, N4H, 0);
        lstm_cell<<<cellBlocks, 256>>>(z, c1, h1h, h1l);
    }

    // ---- Decoder: 8 steps ----
    for (int s = 0; s < NHOR; s++) {
        gemm_f16x3<<<gfull, 256, DSMEM>>>(
            dinh, dinl, KP, dwihh, dwihl, KP, 1,
            h1h, h1l, NH, dwhhh, dwhhl, NH, NTH,
            db, z, N4H, 0);
        lstm_cell<<<cellBlocks, 256>>>(z, c1, h1h, h1l);

        gemm_f16x3<<<ggate, 256, DSMEM>>>(
            h1h, h1l, NH, gw1h, gw1l, NH, NTH,
            (const __half*)nullptr, (const __half*)nullptr, 0,
            (const __half*)nullptr, (const __half*)nullptr, 0, 0,
            gb1, gh, NHH, 1);
        gemm_f16x3<<<gfull, 256, DSMEM>>>(
            h1h, h1l, NH, tw1h, tw1l, NH, NTH,
            (const __half*)nullptr, (const __half*)nullptr, 0,
            (const __half*)nullptr, (const __half*)nullptr, 0, 0,
            tb1, et, N4H, 1);
        gemm_f16x3<<<gfull, 256, DSMEM>>>(
            h1h, h1l, NH, iw1h, iw1l, NH, NTH,
            (const __half*)nullptr, (const __half*)nullptr, 0,
            (const __half*)nullptr, (const __half*)nullptr, 0, 0,
            ib1, ei, N4H, 1);
        gemm_f16x3<<<gfull, 256, DSMEM>>>(
            h1h, h1l, NH, ww1h, ww1l, NH, NTH,
            (const __half*)nullptr, (const __half*)nullptr, 0,
            (const __half*)nullptr, (const __half*)nullptr, 0, 0,
            wb1, ew, N4H, 1);

        gates_kernel<<<NB / 8, 256>>>(gh, gW2, gb2, gates, gsum);
        combine_kernel<<<NB / 8, 256>>>(et, ei, ew, tW2, tb2, iW2, ib2, wW2, wb2,
                                        gates, trk, dw, wa, dinh, dinl, s);
    }

    final_kernel<<<(NB * 40 + 255) / 256, 256>>>(trk, dw, wa, gsum, out);
}